// round 11
// baseline (speedup 1.0000x reference)
#include <cuda_runtime.h>
#include <math.h>
#include <stdint.h>

#define N_ROI 256
#define CCH   256
#define DIN   12544   // 256*49
#define DH    4096
#define NLOC  84
#define NCLS  21
#define NHEAD 105
#define NHPAD 128
#define KS6   14      // fc6 split-K  (klen 896, 28 kt)  -> 896 CTAs
#define KS7   8       // fc7 split-K  (klen 512, 16 kt)  -> 512 CTAs
#define HSPLIT 64     // head split-K (klen 64, 2 kt)

// Scratch (no allocations allowed in kernel_launch)
__device__ float g_pooled[N_ROI * DIN];
__device__ float g_fc6[N_ROI * DH];
__device__ float g_fc7[N_ROI * DH];
__device__ float g_part[16 * N_ROI * DH];
__device__ float g_whead[DH * NHPAD];
__device__ float g_headpart[HSPLIT * N_ROI * NHPAD];
__device__ float g_t3[100 * 100 * CCH];   // transposed feat maps: [H*W][C]
__device__ float g_t4[50 * 50 * CCH];
__device__ float g_t5[25 * 25 * CCH];

static __device__ __forceinline__ float tf32r(float x) {
    float r;
    asm("cvt.rna.tf32.f32 %0, %1;" : "=f"(r) : "f"(x));
    return r;
}

// ---------------------------------------------------------------------------
// Fused tiled transpose of all 3 feature maps: in[C][P] -> out[P][C]
// ---------------------------------------------------------------------------
__global__ __launch_bounds__(256) void transpose_feat_kernel(
    const float* __restrict__ f3, const float* __restrict__ f4,
    const float* __restrict__ f5,
    float* __restrict__ t3, float* __restrict__ t4, float* __restrict__ t5)
{
    __shared__ float t[32][33];
    int bx = blockIdx.x;
    const float* in; float* out; int P;
    if (bx < 313)      { in = f3; out = t3; P = 10000; }
    else if (bx < 392) { in = f4; out = t4; P = 2500; bx -= 313; }
    else               { in = f5; out = t5; P = 625;  bx -= 392; }

    const int p0 = bx * 32;
    const int c0 = blockIdx.y * 32;
    const int x = threadIdx.x;      // 0..31
    const int y = threadIdx.y;      // 0..7

    #pragma unroll
    for (int i = 0; i < 32; i += 8) {
        const int p = p0 + x;
        t[y + i][x] = (p < P) ? in[(size_t)(c0 + y + i) * P + p] : 0.0f;
    }
    __syncthreads();
    #pragma unroll
    for (int i = 0; i < 32; i += 8) {
        const int p = p0 + y + i;
        if (p < P) out[(size_t)p * CCH + c0 + x] = t[x][y + i];
    }
}

// ---------------------------------------------------------------------------
// RoI max-pool over FPN levels, channel-interleaved (coalesced) layout.
// One block per roi, one thread per channel. Output tf32-rounded.
// ---------------------------------------------------------------------------
__global__ void roi_pool_kernel(const float* __restrict__ t3,
                                const float* __restrict__ t4,
                                const float* __restrict__ t5,
                                const float* __restrict__ rois,
                                float* __restrict__ pooled)
{
    const int n = blockIdx.x;
    const int c = threadIdx.x;

    const float y1 = rois[n * 4 + 0];
    const float x1 = rois[n * 4 + 1];
    const float y2 = rois[n * 4 + 2];
    const float x2 = rois[n * 4 + 3];

    const float Hr = y2 - y1;
    const float Wr = x2 - x1;
    float lv = rintf(logf(sqrtf(Hr * Wr) / 224.0f) + 5.0f);
    lv = fminf(fmaxf(lv, 3.0f), 5.0f);
    const int l = (int)lv - 3;

    const float scale = (l == 0) ? 0.125f : (l == 1 ? 0.0625f : 0.03125f);
    const int   hw    = (l == 0) ? 100    : (l == 1 ? 50      : 25);
    const float* fmap = (l == 0) ? t3     : (l == 1 ? t4      : t5);

    const float ys = floorf(y1 * scale + 0.5f);
    const float xs = floorf(x1 * scale + 0.5f);
    const float ye = floorf(y2 * scale + 0.5f);
    const float xe = floorf(x2 * scale + 0.5f);
    const float bh = fmaxf(ye - ys + 1.0f, 1.0f) * (1.0f / 7.0f);
    const float bw = fmaxf(xe - xs + 1.0f, 1.0f) * (1.0f / 7.0f);

    float* orow = pooled + (size_t)n * DIN + (size_t)c * 49;

    #pragma unroll
    for (int ph = 0; ph < 7; ph++) {
        int h0 = (int)fminf(fmaxf(floorf((float)ph * bh) + ys, 0.0f), (float)hw);
        int h1 = (int)fminf(fmaxf(ceilf((float)(ph + 1) * bh) + ys, 0.0f), (float)hw);
        #pragma unroll
        for (int pw = 0; pw < 7; pw++) {
            int w0 = (int)fminf(fmaxf(floorf((float)pw * bw) + xs, 0.0f), (float)hw);
            int w1 = (int)fminf(fmaxf(ceilf((float)(pw + 1) * bw) + xs, 0.0f), (float)hw);
            float m;
            if (h1 <= h0 || w1 <= w0) {
                m = 0.0f;
            } else {
                m = -INFINITY;
                for (int r = h0; r < h1; r++) {
                    const float* rowp = fmap + ((size_t)r * hw) * CCH + c;
                    for (int q = w0; q < w1; q++)
                        m = fmaxf(m, rowp[(size_t)q * CCH]);
                }
            }
            orow[ph * 7 + pw] = tf32r(m);
        }
    }
}

// ---------------------------------------------------------------------------
// TF32 mma.sync GEMM, cp.async 3-stage pipeline, 2 CTAs/SM.
//   Block tile 128x128x32, 8 warps (2m x 4n), warp tile 64x32 (4x4 m16n8k8).
//   Loop order: wait -> sync -> ISSUE kt+2 -> compute kt  (full overlap).
//   A operand assumed pre-rounded to tf32; B rounded (cvt.rna) on frag load.
//   mode: bit0 = relu, bit1 = round output to tf32, bit2 = partial
//         (no bias, C += blockIdx.z * M * N; K-slice = [z*klen, (z+1)*klen))
// ---------------------------------------------------------------------------
#define BM 128
#define BN 128
#define BK 32
#define TPB 256
#define ASTR 36
#define BSTR 136
#define A_ST (BM * ASTR)                 // 4608 floats
#define B_ST (BK * BSTR)                 // 4352 floats
#define STAGE_FLOATS (A_ST + B_ST)       // 8960 floats = 35840 B
#define STAGES 3
#define SMEM_BYTES (STAGES * STAGE_FLOATS * 4)   // 107520 B -> 2 CTAs/SM

static __device__ __forceinline__ void cpasync16(uint32_t d, const void* s) {
    asm volatile("cp.async.cg.shared.global [%0], [%1], 16;"
                 :: "r"(d), "l"(s));
}

static __device__ __forceinline__ void mma16n8k8(
    float& c0, float& c1, float& c2, float& c3,
    uint32_t a0, uint32_t a1, uint32_t a2, uint32_t a3,
    uint32_t b0, uint32_t b1)
{
    asm volatile(
        "mma.sync.aligned.m16n8k8.row.col.f32.tf32.tf32.f32 "
        "{%0,%1,%2,%3},{%4,%5,%6,%7},{%8,%9},{%0,%1,%2,%3};"
        : "+f"(c0), "+f"(c1), "+f"(c2), "+f"(c3)
        : "r"(a0), "r"(a1), "r"(a2), "r"(a3), "r"(b0), "r"(b1));
}

__global__ __launch_bounds__(TPB, 2) void gemm_tf32_kernel(
    const float* __restrict__ A, const float* __restrict__ B,
    const float* __restrict__ bias, float* __restrict__ C,
    int M, int N, int lda, int ldb, int klen, int mode)
{
    extern __shared__ __align__(16) float sm[];
    uint32_t smbase;
    asm("{ .reg .u64 t; cvta.to.shared.u64 t, %1; cvt.u32.u64 %0, t; }"
        : "=r"(smbase) : "l"(sm));

    const int tid  = threadIdx.x;
    const int wid  = tid >> 5;
    const int lane = tid & 31;
    const int gid  = lane >> 2;
    const int tig  = lane & 3;
    const int wm = wid & 1;       // 2 m-warps (64 rows each)
    const int wn = wid >> 1;      // 4 n-warps (32 cols each)

    const int m0 = blockIdx.y * BM;
    const int n0 = blockIdx.x * BN;
    const int kstart = blockIdx.z * klen;
    if (mode & 4) C += (size_t)blockIdx.z * M * N;

    // cp.async tile mapping (256 threads, 4 passes each for A and B)
    const int arow  = tid >> 3;           // 0..31 ; +32p
    const int acol4 = (tid & 7) * 4;
    const int brow  = tid >> 5;           // 0..7  ; +8p
    const int bcol4 = (tid & 31) * 4;

    const float* Agp = A + (size_t)(m0 + arow) * lda + kstart + acol4;
    const float* Bgp = B + (size_t)(kstart + brow) * ldb + n0 + bcol4;
    const uint32_t Asd = smbase + (uint32_t)(arow * ASTR + acol4) * 4u;
    const uint32_t Bsd = smbase + (uint32_t)(A_ST + brow * BSTR + bcol4) * 4u;

    const int nkt = klen / BK;

    float acc[4][4][4];
    #pragma unroll
    for (int i = 0; i < 4; i++)
        #pragma unroll
        for (int j = 0; j < 4; j++)
            #pragma unroll
            for (int q = 0; q < 4; q++) acc[i][j][q] = 0.0f;

    // prologue: stages 0..1
    #pragma unroll
    for (int s = 0; s < STAGES - 1; s++) {
        if (s < nkt) {
            const uint32_t so = (uint32_t)(s * STAGE_FLOATS) * 4u;
            #pragma unroll
            for (int p = 0; p < 4; p++)
                cpasync16(Asd + so + (uint32_t)(p * 32 * ASTR) * 4u,
                          Agp + (size_t)(p * 32) * lda + s * BK);
            #pragma unroll
            for (int p = 0; p < 4; p++)
                cpasync16(Bsd + so + (uint32_t)(p * 8 * BSTR) * 4u,
                          Bgp + (size_t)(s * BK + p * 8) * ldb);
        }
        asm volatile("cp.async.commit_group;");
    }

    const int ra = wm * 64 + gid;
    const int nb = wn * 32 + gid;

    int cs = 0;          // compute slot
    int ws = STAGES - 1; // write slot (= slot of kt+2; holds kt-1's consumed data)
    for (int kt = 0; kt < nkt; kt++) {
        asm volatile("cp.async.wait_group %0;" :: "n"(STAGES - 2));
        __syncthreads();

        // issue stage kt+2 FIRST so its gmem flight overlaps this kt's compute.
        // Slot ws held kt-1's data; the sync above proves all warps are done with it.
        {
            const int kn = kt + STAGES - 1;
            if (kn < nkt) {
                const uint32_t so = (uint32_t)(ws * STAGE_FLOATS) * 4u;
                #pragma unroll
                for (int p = 0; p < 4; p++)
                    cpasync16(Asd + so + (uint32_t)(p * 32 * ASTR) * 4u,
                              Agp + (size_t)(p * 32) * lda + kn * BK);
                #pragma unroll
                for (int p = 0; p < 4; p++)
                    cpasync16(Bsd + so + (uint32_t)(p * 8 * BSTR) * 4u,
                              Bgp + (size_t)(kn * BK + p * 8) * ldb);
            }
            asm volatile("cp.async.commit_group;");
        }

        const float* Ab = sm + cs * STAGE_FLOATS;
        const float* Bb = Ab + A_ST;

        #pragma unroll
        for (int ks = 0; ks < 4; ks++) {
            const int ca = ks * 8 + tig;
            uint32_t af[4][4];
            #pragma unroll
            for (int tm = 0; tm < 4; tm++) {
                const float* ap = Ab + (ra + tm * 16) * ASTR + ca;
                af[tm][0] = __float_as_uint(ap[0]);
                af[tm][1] = __float_as_uint(ap[8 * ASTR]);
                af[tm][2] = __float_as_uint(ap[4]);
                af[tm][3] = __float_as_uint(ap[8 * ASTR + 4]);
            }
            uint32_t bf[4][2];
            #pragma unroll
            for (int tn = 0; tn < 4; tn++) {
                const float* bp = Bb + ca * BSTR + nb + tn * 8;
                bf[tn][0] = __float_as_uint(tf32r(bp[0]));
                bf[tn][1] = __float_as_uint(tf32r(bp[4 * BSTR]));
            }
            #pragma unroll
            for (int tm = 0; tm < 4; tm++)
                #pragma unroll
                for (int tn = 0; tn < 4; tn++)
                    mma16n8k8(acc[tm][tn][0], acc[tm][tn][1], acc[tm][tn][2], acc[tm][tn][3],
                              af[tm][0], af[tm][1], af[tm][2], af[tm][3],
                              bf[tn][0], bf[tn][1]);
        }

        if (++cs == STAGES) cs = 0;
        if (++ws == STAGES) ws = 0;
    }

    // epilogue
    const int relu  = mode & 1;
    const int rnd   = mode & 2;
    const int part  = mode & 4;
    #pragma unroll
    for (int tm = 0; tm < 4; tm++) {
        const int rbase = m0 + wm * 64 + tm * 16 + gid;
        #pragma unroll
        for (int tn = 0; tn < 4; tn++) {
            const int cb = n0 + wn * 32 + tn * 8 + tig * 2;
            float b0 = 0.0f, b1 = 0.0f;
            if (!part) { b0 = bias[cb]; b1 = bias[cb + 1]; }
            float v0 = acc[tm][tn][0] + b0, v1 = acc[tm][tn][1] + b1;
            float v2 = acc[tm][tn][2] + b0, v3 = acc[tm][tn][3] + b1;
            if (relu) {
                v0 = fmaxf(v0, 0.0f); v1 = fmaxf(v1, 0.0f);
                v2 = fmaxf(v2, 0.0f); v3 = fmaxf(v3, 0.0f);
            }
            if (rnd) {
                v0 = tf32r(v0); v1 = tf32r(v1);
                v2 = tf32r(v2); v3 = tf32r(v3);
            }
            *(float2*)(C + (size_t)rbase * N + cb)       = make_float2(v0, v1);
            *(float2*)(C + (size_t)(rbase + 8) * N + cb) = make_float2(v2, v3);
        }
    }
}

// ---------------------------------------------------------------------------
// Reduce npart fp32 partials of an fc layer (float4): relu(sum+bias), tf32.
// ---------------------------------------------------------------------------
__global__ __launch_bounds__(256) void reduce_fc_kernel(
    const float* __restrict__ part, const float* __restrict__ bias,
    float* __restrict__ dst, int npart)
{
    const int v = blockIdx.x * 256 + threadIdx.x;     // over N_ROI*DH/4
    const int idx = v * 4;
    float4 s = *(const float4*)(bias + (idx & (DH - 1)));
    for (int p = 0; p < npart; p++) {
        float4 t = *(const float4*)(part + (size_t)p * N_ROI * DH + idx);
        s.x += t.x; s.y += t.y; s.z += t.z; s.w += t.w;
    }
    float4 o;
    o.x = tf32r(fmaxf(s.x, 0.0f));
    o.y = tf32r(fmaxf(s.y, 0.0f));
    o.z = tf32r(fmaxf(s.z, 0.0f));
    o.w = tf32r(fmaxf(s.w, 0.0f));
    *(float4*)(dst + idx) = o;
}

// ---------------------------------------------------------------------------
// Pack head weights: Whead[k][0:84]=Wloc, [84:105]=Wcls, [105:128]=0.
// ---------------------------------------------------------------------------
__global__ __launch_bounds__(256) void pack_head_kernel(
    const float* __restrict__ Wloc, const float* __restrict__ Wcls,
    float* __restrict__ Wh)
{
    const int idx = blockIdx.x * 256 + threadIdx.x;
    const int k = idx >> 7;
    const int j = idx & 127;
    float v = 0.0f;
    if (j < NLOC)       v = Wloc[(size_t)k * NLOC + j];
    else if (j < NHEAD) v = Wcls[(size_t)k * NCLS + (j - NLOC)];
    Wh[idx] = v;
}

// ---------------------------------------------------------------------------
// Reduce head split-K partials, add bias, scatter into output layout
// [256*84 loc][256*21 cls].
// ---------------------------------------------------------------------------
__global__ __launch_bounds__(128) void reduce_head_kernel(
    const float* __restrict__ part,
    const float* __restrict__ bloc, const float* __restrict__ bcls,
    float* __restrict__ out)
{
    const int n = blockIdx.x;
    const int j = threadIdx.x;
    if (j >= NHEAD) return;
    float s = (j < NLOC) ? bloc[j] : bcls[j - NLOC];
    #pragma unroll 8
    for (int p = 0; p < HSPLIT; p++)
        s += part[(size_t)p * N_ROI * NHPAD + (size_t)n * NHPAD + j];
    if (j < NLOC)
        out[(size_t)n * NLOC + j] = s;
    else
        out[(size_t)N_ROI * NLOC + (size_t)n * NCLS + (j - NLOC)] = s;
}

// ---------------------------------------------------------------------------
extern "C" void kernel_launch(void* const* d_in, const int* in_sizes, int n_in,
                              void* d_out, int out_size)
{
    const float* f3   = (const float*)d_in[0];
    const float* f4   = (const float*)d_in[1];
    const float* f5   = (const float*)d_in[2];
    const float* rois = (const float*)d_in[3];
    const float* Wfc6 = (const float*)d_in[4];
    const float* bfc6 = (const float*)d_in[5];
    const float* Wfc7 = (const float*)d_in[6];
    const float* bfc7 = (const float*)d_in[7];
    const float* Wloc = (const float*)d_in[8];
    const float* bloc = (const float*)d_in[9];
    const float* Wcls = (const float*)d_in[10];
    const float* bcls = (const float*)d_in[11];
    float* out = (float*)d_out;

    float *pooled, *fc6, *fc7, *partb, *whead, *headpart, *t3, *t4, *t5;
    cudaGetSymbolAddress((void**)&pooled, g_pooled);
    cudaGetSymbolAddress((void**)&fc6, g_fc6);
    cudaGetSymbolAddress((void**)&fc7, g_fc7);
    cudaGetSymbolAddress((void**)&partb, g_part);
    cudaGetSymbolAddress((void**)&whead, g_whead);
    cudaGetSymbolAddress((void**)&headpart, g_headpart);
    cudaGetSymbolAddress((void**)&t3, g_t3);
    cudaGetSymbolAddress((void**)&t4, g_t4);
    cudaGetSymbolAddress((void**)&t5, g_t5);

    cudaFuncSetAttribute(gemm_tf32_kernel,
                         cudaFuncAttributeMaxDynamicSharedMemorySize, SMEM_BYTES);

    // 0) pack head weights + fused transpose of all feature maps to [P][C]
    pack_head_kernel<<<(DH * NHPAD) / 256, 256>>>(Wloc, Wcls, whead);
    transpose_feat_kernel<<<dim3(412, 8), dim3(32, 8)>>>(f3, f4, f5, t3, t4, t5);

    // 1) roi_pool (coalesced, tf32-rounded output)
    roi_pool_kernel<<<N_ROI, CCH>>>(t3, t4, t5, rois, pooled);

    // 2) fc6 partials = pooled @ Wfc6  (K=12544 split 14x896), then reduce+bias+relu
    gemm_tf32_kernel<<<dim3(DH / BN, N_ROI / BM, KS6), TPB, SMEM_BYTES>>>(
        pooled, Wfc6, nullptr, partb, N_ROI, DH, DIN, DH, DIN / KS6, 4);
    reduce_fc_kernel<<<(N_ROI * DH) / 1024, 256>>>(partb, bfc6, fc6, KS6);

    // 3) fc7 partials = fc6 @ Wfc7     (K=4096 split 8x512), then reduce+bias+relu
    gemm_tf32_kernel<<<dim3(DH / BN, N_ROI / BM, KS7), TPB, SMEM_BYTES>>>(
        fc6, Wfc7, nullptr, partb, N_ROI, DH, DH, DH, DH / KS7, 4);
    reduce_fc_kernel<<<(N_ROI * DH) / 1024, 256>>>(partb, bfc7, fc7, KS7);

    // 4) head partials = fc7 @ Whead   (M=256, N=128, K split 64x64)
    gemm_tf32_kernel<<<dim3(NHPAD / BN, N_ROI / BM, HSPLIT), TPB, SMEM_BYTES>>>(
        fc7, whead, nullptr, headpart, N_ROI, NHPAD, DH, NHPAD, DH / HSPLIT, 4);

    // 5) reduce + bias + scatter
    reduce_head_kernel<<<N_ROI, 128>>>(headpart, bloc, bcls, out);
}

// round 12
// speedup vs baseline: 1.2206x; 1.2206x over previous
#include <cuda_runtime.h>
#include <math.h>
#include <stdint.h>

#define N_ROI 256
#define CCH   256
#define DIN   12544   // 256*49
#define DH    4096
#define NLOC  84
#define NCLS  21
#define NHEAD 105
#define NHPAD 128
#define KS6   14      // fc6 split-K  (klen 896, 28 kt)  -> 896 CTAs
#define KS7   8       // fc7 split-K  (klen 512, 16 kt)  -> 512 CTAs
#define HSPLIT 64     // head split-K (klen 64, 2 kt)

// Scratch (no allocations allowed in kernel_launch)
__device__ float g_pooled[N_ROI * DIN];
__device__ float g_fc6[N_ROI * DH];
__device__ float g_fc7[N_ROI * DH];
__device__ float g_part[16 * N_ROI * DH];
__device__ float g_whead[DH * NHPAD];
__device__ float g_headpart[HSPLIT * N_ROI * NHPAD];
__device__ float g_t3[100 * 100 * CCH];   // transposed feat maps: [H*W][C]
__device__ float g_t4[50 * 50 * CCH];
__device__ float g_t5[25 * 25 * CCH];

static __device__ __forceinline__ float tf32r(float x) {
    float r;
    asm("cvt.rna.tf32.f32 %0, %1;" : "=f"(r) : "f"(x));
    return r;
}

// ---------------------------------------------------------------------------
// Fused tiled transpose of all 3 feature maps: in[C][P] -> out[P][C]
// ---------------------------------------------------------------------------
__global__ __launch_bounds__(256) void transpose_feat_kernel(
    const float* __restrict__ f3, const float* __restrict__ f4,
    const float* __restrict__ f5,
    float* __restrict__ t3, float* __restrict__ t4, float* __restrict__ t5)
{
    __shared__ float t[32][33];
    int bx = blockIdx.x;
    const float* in; float* out; int P;
    if (bx < 313)      { in = f3; out = t3; P = 10000; }
    else if (bx < 392) { in = f4; out = t4; P = 2500; bx -= 313; }
    else               { in = f5; out = t5; P = 625;  bx -= 392; }

    const int p0 = bx * 32;
    const int c0 = blockIdx.y * 32;
    const int x = threadIdx.x;      // 0..31
    const int y = threadIdx.y;      // 0..7

    #pragma unroll
    for (int i = 0; i < 32; i += 8) {
        const int p = p0 + x;
        t[y + i][x] = (p < P) ? in[(size_t)(c0 + y + i) * P + p] : 0.0f;
    }
    __syncthreads();
    #pragma unroll
    for (int i = 0; i < 32; i += 8) {
        const int p = p0 + y + i;
        if (p < P) out[(size_t)p * CCH + c0 + x] = t[x][y + i];
    }
}

// ---------------------------------------------------------------------------
// RoI max-pool, channel-interleaved layout, split over (roi, ph).
// grid = (N_ROI, 7); one thread per channel; each thread does 7 pw bins.
// Output tf32-rounded.
// ---------------------------------------------------------------------------
__global__ void roi_pool_kernel(const float* __restrict__ t3,
                                const float* __restrict__ t4,
                                const float* __restrict__ t5,
                                const float* __restrict__ rois,
                                float* __restrict__ pooled)
{
    const int n  = blockIdx.x;
    const int ph = blockIdx.y;
    const int c  = threadIdx.x;

    const float y1 = rois[n * 4 + 0];
    const float x1 = rois[n * 4 + 1];
    const float y2 = rois[n * 4 + 2];
    const float x2 = rois[n * 4 + 3];

    const float Hr = y2 - y1;
    const float Wr = x2 - x1;
    float lv = rintf(logf(sqrtf(Hr * Wr) / 224.0f) + 5.0f);
    lv = fminf(fmaxf(lv, 3.0f), 5.0f);
    const int l = (int)lv - 3;

    const float scale = (l == 0) ? 0.125f : (l == 1 ? 0.0625f : 0.03125f);
    const int   hw    = (l == 0) ? 100    : (l == 1 ? 50      : 25);
    const float* fmap = (l == 0) ? t3     : (l == 1 ? t4      : t5);

    const float ys = floorf(y1 * scale + 0.5f);
    const float xs = floorf(x1 * scale + 0.5f);
    const float ye = floorf(y2 * scale + 0.5f);
    const float xe = floorf(x2 * scale + 0.5f);
    const float bh = fmaxf(ye - ys + 1.0f, 1.0f) * (1.0f / 7.0f);
    const float bw = fmaxf(xe - xs + 1.0f, 1.0f) * (1.0f / 7.0f);

    float* orow = pooled + (size_t)n * DIN + (size_t)c * 49 + ph * 7;

    const int h0 = (int)fminf(fmaxf(floorf((float)ph * bh) + ys, 0.0f), (float)hw);
    const int h1 = (int)fminf(fmaxf(ceilf((float)(ph + 1) * bh) + ys, 0.0f), (float)hw);

    #pragma unroll
    for (int pw = 0; pw < 7; pw++) {
        int w0 = (int)fminf(fmaxf(floorf((float)pw * bw) + xs, 0.0f), (float)hw);
        int w1 = (int)fminf(fmaxf(ceilf((float)(pw + 1) * bw) + xs, 0.0f), (float)hw);
        float m;
        if (h1 <= h0 || w1 <= w0) {
            m = 0.0f;
        } else {
            m = -INFINITY;
            for (int r = h0; r < h1; r++) {
                const float* rowp = fmap + ((size_t)r * hw) * CCH + c;
                for (int q = w0; q < w1; q++)
                    m = fmaxf(m, rowp[(size_t)q * CCH]);
            }
        }
        orow[pw] = tf32r(m);
    }
}

// ---------------------------------------------------------------------------
// TF32 mma.sync GEMM, cp.async 3-stage pipeline, 2 CTAs/SM.
//   Block tile 128x128x32, 8 warps (2m x 4n), warp tile 64x32 (4x4 m16n8k8).
//   Loop order (round-10, measured best): wait -> sync -> compute -> issue.
//   A operand assumed pre-rounded to tf32; B rounded (cvt.rna) on frag load.
//   mode: bit0 = relu, bit1 = round output to tf32, bit2 = partial
//         (no bias, C += blockIdx.z * M * N; K-slice = [z*klen, (z+1)*klen))
// ---------------------------------------------------------------------------
#define BM 128
#define BN 128
#define BK 32
#define TPB 256
#define ASTR 36
#define BSTR 136
#define A_ST (BM * ASTR)                 // 4608 floats
#define B_ST (BK * BSTR)                 // 4352 floats
#define STAGE_FLOATS (A_ST + B_ST)       // 8960 floats = 35840 B
#define STAGES 3
#define SMEM_BYTES (STAGES * STAGE_FLOATS * 4)   // 107520 B -> 2 CTAs/SM

static __device__ __forceinline__ void cpasync16(uint32_t d, const void* s) {
    asm volatile("cp.async.cg.shared.global [%0], [%1], 16;"
                 :: "r"(d), "l"(s));
}

static __device__ __forceinline__ void mma16n8k8(
    float& c0, float& c1, float& c2, float& c3,
    uint32_t a0, uint32_t a1, uint32_t a2, uint32_t a3,
    uint32_t b0, uint32_t b1)
{
    asm volatile(
        "mma.sync.aligned.m16n8k8.row.col.f32.tf32.tf32.f32 "
        "{%0,%1,%2,%3},{%4,%5,%6,%7},{%8,%9},{%0,%1,%2,%3};"
        : "+f"(c0), "+f"(c1), "+f"(c2), "+f"(c3)
        : "r"(a0), "r"(a1), "r"(a2), "r"(a3), "r"(b0), "r"(b1));
}

__global__ __launch_bounds__(TPB, 2) void gemm_tf32_kernel(
    const float* __restrict__ A, const float* __restrict__ B,
    const float* __restrict__ bias, float* __restrict__ C,
    int M, int N, int lda, int ldb, int klen, int mode)
{
    extern __shared__ __align__(16) float sm[];
    uint32_t smbase;
    asm("{ .reg .u64 t; cvta.to.shared.u64 t, %1; cvt.u32.u64 %0, t; }"
        : "=r"(smbase) : "l"(sm));

    const int tid  = threadIdx.x;
    const int wid  = tid >> 5;
    const int lane = tid & 31;
    const int gid  = lane >> 2;
    const int tig  = lane & 3;
    const int wm = wid & 1;       // 2 m-warps (64 rows each)
    const int wn = wid >> 1;      // 4 n-warps (32 cols each)

    const int m0 = blockIdx.y * BM;
    const int n0 = blockIdx.x * BN;
    const int kstart = blockIdx.z * klen;
    if (mode & 4) C += (size_t)blockIdx.z * M * N;

    // cp.async tile mapping (256 threads, 4 passes each for A and B)
    const int arow  = tid >> 3;           // 0..31 ; +32p
    const int acol4 = (tid & 7) * 4;
    const int brow  = tid >> 5;           // 0..7  ; +8p
    const int bcol4 = (tid & 31) * 4;

    const float* Agp = A + (size_t)(m0 + arow) * lda + kstart + acol4;
    const float* Bgp = B + (size_t)(kstart + brow) * ldb + n0 + bcol4;
    const uint32_t Asd = smbase + (uint32_t)(arow * ASTR + acol4) * 4u;
    const uint32_t Bsd = smbase + (uint32_t)(A_ST + brow * BSTR + bcol4) * 4u;

    const int nkt = klen / BK;

    float acc[4][4][4];
    #pragma unroll
    for (int i = 0; i < 4; i++)
        #pragma unroll
        for (int j = 0; j < 4; j++)
            #pragma unroll
            for (int q = 0; q < 4; q++) acc[i][j][q] = 0.0f;

    // prologue: stages 0..1
    #pragma unroll
    for (int s = 0; s < STAGES - 1; s++) {
        if (s < nkt) {
            const uint32_t so = (uint32_t)(s * STAGE_FLOATS) * 4u;
            #pragma unroll
            for (int p = 0; p < 4; p++)
                cpasync16(Asd + so + (uint32_t)(p * 32 * ASTR) * 4u,
                          Agp + (size_t)(p * 32) * lda + s * BK);
            #pragma unroll
            for (int p = 0; p < 4; p++)
                cpasync16(Bsd + so + (uint32_t)(p * 8 * BSTR) * 4u,
                          Bgp + (size_t)(s * BK + p * 8) * ldb);
        }
        asm volatile("cp.async.commit_group;");
    }

    const int ra = wm * 64 + gid;
    const int nb = wn * 32 + gid;

    int cs = 0;          // compute slot
    int ws = STAGES - 1; // write slot (= slot of kt+2; holds kt-1's consumed data)
    for (int kt = 0; kt < nkt; kt++) {
        asm volatile("cp.async.wait_group %0;" :: "n"(STAGES - 2));
        __syncthreads();

        const float* Ab = sm + cs * STAGE_FLOATS;
        const float* Bb = Ab + A_ST;

        #pragma unroll
        for (int ks = 0; ks < 4; ks++) {
            const int ca = ks * 8 + tig;
            uint32_t af[4][4];
            #pragma unroll
            for (int tm = 0; tm < 4; tm++) {
                const float* ap = Ab + (ra + tm * 16) * ASTR + ca;
                af[tm][0] = __float_as_uint(ap[0]);
                af[tm][1] = __float_as_uint(ap[8 * ASTR]);
                af[tm][2] = __float_as_uint(ap[4]);
                af[tm][3] = __float_as_uint(ap[8 * ASTR + 4]);
            }
            uint32_t bf[4][2];
            #pragma unroll
            for (int tn = 0; tn < 4; tn++) {
                const float* bp = Bb + ca * BSTR + nb + tn * 8;
                bf[tn][0] = __float_as_uint(tf32r(bp[0]));
                bf[tn][1] = __float_as_uint(tf32r(bp[4 * BSTR]));
            }
            #pragma unroll
            for (int tm = 0; tm < 4; tm++)
                #pragma unroll
                for (int tn = 0; tn < 4; tn++)
                    mma16n8k8(acc[tm][tn][0], acc[tm][tn][1], acc[tm][tn][2], acc[tm][tn][3],
                              af[tm][0], af[tm][1], af[tm][2], af[tm][3],
                              bf[tn][0], bf[tn][1]);
        }

        // issue stage kt+2 into slot ws (freed: computed at kt-1, all warps past sync)
        {
            const int kn = kt + STAGES - 1;
            if (kn < nkt) {
                const uint32_t so = (uint32_t)(ws * STAGE_FLOATS) * 4u;
                #pragma unroll
                for (int p = 0; p < 4; p++)
                    cpasync16(Asd + so + (uint32_t)(p * 32 * ASTR) * 4u,
                              Agp + (size_t)(p * 32) * lda + kn * BK);
                #pragma unroll
                for (int p = 0; p < 4; p++)
                    cpasync16(Bsd + so + (uint32_t)(p * 8 * BSTR) * 4u,
                              Bgp + (size_t)(kn * BK + p * 8) * ldb);
            }
            asm volatile("cp.async.commit_group;");
        }
        if (++cs == STAGES) cs = 0;
        if (++ws == STAGES) ws = 0;
    }

    // epilogue
    const int relu  = mode & 1;
    const int rnd   = mode & 2;
    const int part  = mode & 4;
    #pragma unroll
    for (int tm = 0; tm < 4; tm++) {
        const int rbase = m0 + wm * 64 + tm * 16 + gid;
        #pragma unroll
        for (int tn = 0; tn < 4; tn++) {
            const int cb = n0 + wn * 32 + tn * 8 + tig * 2;
            float b0 = 0.0f, b1 = 0.0f;
            if (!part) { b0 = bias[cb]; b1 = bias[cb + 1]; }
            float v0 = acc[tm][tn][0] + b0, v1 = acc[tm][tn][1] + b1;
            float v2 = acc[tm][tn][2] + b0, v3 = acc[tm][tn][3] + b1;
            if (relu) {
                v0 = fmaxf(v0, 0.0f); v1 = fmaxf(v1, 0.0f);
                v2 = fmaxf(v2, 0.0f); v3 = fmaxf(v3, 0.0f);
            }
            if (rnd) {
                v0 = tf32r(v0); v1 = tf32r(v1);
                v2 = tf32r(v2); v3 = tf32r(v3);
            }
            *(float2*)(C + (size_t)rbase * N + cb)       = make_float2(v0, v1);
            *(float2*)(C + (size_t)(rbase + 8) * N + cb) = make_float2(v2, v3);
        }
    }
}

// ---------------------------------------------------------------------------
// Reduce npart fp32 partials of an fc layer (float4): relu(sum+bias), tf32.
// ---------------------------------------------------------------------------
__global__ __launch_bounds__(256) void reduce_fc_kernel(
    const float* __restrict__ part, const float* __restrict__ bias,
    float* __restrict__ dst, int npart)
{
    const int v = blockIdx.x * 256 + threadIdx.x;     // over N_ROI*DH/4
    const int idx = v * 4;
    float4 s = *(const float4*)(bias + (idx & (DH - 1)));
    for (int p = 0; p < npart; p++) {
        float4 t = *(const float4*)(part + (size_t)p * N_ROI * DH + idx);
        s.x += t.x; s.y += t.y; s.z += t.z; s.w += t.w;
    }
    float4 o;
    o.x = tf32r(fmaxf(s.x, 0.0f));
    o.y = tf32r(fmaxf(s.y, 0.0f));
    o.z = tf32r(fmaxf(s.z, 0.0f));
    o.w = tf32r(fmaxf(s.w, 0.0f));
    *(float4*)(dst + idx) = o;
}

// ---------------------------------------------------------------------------
// Pack head weights: Whead[k][0:84]=Wloc, [84:105]=Wcls, [105:128]=0.
// ---------------------------------------------------------------------------
__global__ __launch_bounds__(256) void pack_head_kernel(
    const float* __restrict__ Wloc, const float* __restrict__ Wcls,
    float* __restrict__ Wh)
{
    const int idx = blockIdx.x * 256 + threadIdx.x;
    const int k = idx >> 7;
    const int j = idx & 127;
    float v = 0.0f;
    if (j < NLOC)       v = Wloc[(size_t)k * NLOC + j];
    else if (j < NHEAD) v = Wcls[(size_t)k * NCLS + (j - NLOC)];
    Wh[idx] = v;
}

// ---------------------------------------------------------------------------
// Reduce head split-K partials (float4), add bias, scatter into output
// layout [256*84 loc][256*21 cls]. 32 threads x 4 cols per block.
// ---------------------------------------------------------------------------
__global__ __launch_bounds__(32) void reduce_head_kernel(
    const float* __restrict__ part,
    const float* __restrict__ bloc, const float* __restrict__ bcls,
    float* __restrict__ out)
{
    const int n  = blockIdx.x;
    const int j4 = threadIdx.x * 4;
    float4 s = make_float4(0.f, 0.f, 0.f, 0.f);
    #pragma unroll 8
    for (int p = 0; p < HSPLIT; p++) {
        float4 t = *(const float4*)(part + (size_t)p * N_ROI * NHPAD
                                         + (size_t)n * NHPAD + j4);
        s.x += t.x; s.y += t.y; s.z += t.z; s.w += t.w;
    }
    float vals[4] = {s.x, s.y, s.z, s.w};
    #pragma unroll
    for (int q = 0; q < 4; q++) {
        const int j = j4 + q;
        if (j < NLOC)
            out[(size_t)n * NLOC + j] = vals[q] + bloc[j];
        else if (j < NHEAD)
            out[(size_t)N_ROI * NLOC + (size_t)n * NCLS + (j - NLOC)]
                = vals[q] + bcls[j - NLOC];
    }
}

// ---------------------------------------------------------------------------
extern "C" void kernel_launch(void* const* d_in, const int* in_sizes, int n_in,
                              void* d_out, int out_size)
{
    const float* f3   = (const float*)d_in[0];
    const float* f4   = (const float*)d_in[1];
    const float* f5   = (const float*)d_in[2];
    const float* rois = (const float*)d_in[3];
    const float* Wfc6 = (const float*)d_in[4];
    const float* bfc6 = (const float*)d_in[5];
    const float* Wfc7 = (const float*)d_in[6];
    const float* bfc7 = (const float*)d_in[7];
    const float* Wloc = (const float*)d_in[8];
    const float* bloc = (const float*)d_in[9];
    const float* Wcls = (const float*)d_in[10];
    const float* bcls = (const float*)d_in[11];
    float* out = (float*)d_out;

    float *pooled, *fc6, *fc7, *partb, *whead, *headpart, *t3, *t4, *t5;
    cudaGetSymbolAddress((void**)&pooled, g_pooled);
    cudaGetSymbolAddress((void**)&fc6, g_fc6);
    cudaGetSymbolAddress((void**)&fc7, g_fc7);
    cudaGetSymbolAddress((void**)&partb, g_part);
    cudaGetSymbolAddress((void**)&whead, g_whead);
    cudaGetSymbolAddress((void**)&headpart, g_headpart);
    cudaGetSymbolAddress((void**)&t3, g_t3);
    cudaGetSymbolAddress((void**)&t4, g_t4);
    cudaGetSymbolAddress((void**)&t5, g_t5);

    cudaFuncSetAttribute(gemm_tf32_kernel,
                         cudaFuncAttributeMaxDynamicSharedMemorySize, SMEM_BYTES);

    // 0) pack head weights + fused transpose of all feature maps to [P][C]
    pack_head_kernel<<<(DH * NHPAD) / 256, 256>>>(Wloc, Wcls, whead);
    transpose_feat_kernel<<<dim3(412, 8), dim3(32, 8)>>>(f3, f4, f5, t3, t4, t5);

    // 1) roi_pool (coalesced, split over ph, tf32-rounded output)
    roi_pool_kernel<<<dim3(N_ROI, 7), CCH>>>(t3, t4, t5, rois, pooled);

    // 2) fc6 partials = pooled @ Wfc6  (K=12544 split 14x896), then reduce+bias+relu
    gemm_tf32_kernel<<<dim3(DH / BN, N_ROI / BM, KS6), TPB, SMEM_BYTES>>>(
        pooled, Wfc6, nullptr, partb, N_ROI, DH, DIN, DH, DIN / KS6, 4);
    reduce_fc_kernel<<<(N_ROI * DH) / 1024, 256>>>(partb, bfc6, fc6, KS6);

    // 3) fc7 partials = fc6 @ Wfc7     (K=4096 split 8x512), then reduce+bias+relu
    gemm_tf32_kernel<<<dim3(DH / BN, N_ROI / BM, KS7), TPB, SMEM_BYTES>>>(
        fc6, Wfc7, nullptr, partb, N_ROI, DH, DH, DH, DH / KS7, 4);
    reduce_fc_kernel<<<(N_ROI * DH) / 1024, 256>>>(partb, bfc7, fc7, KS7);

    // 4) head partials = fc7 @ Whead   (M=256, N=128, K split 64x64)
    gemm_tf32_kernel<<<dim3(NHPAD / BN, N_ROI / BM, HSPLIT), TPB, SMEM_BYTES>>>(
        fc7, whead, nullptr, headpart, N_ROI, NHPAD, DH, NHPAD, DH / HSPLIT, 4);

    // 5) reduce + bias + scatter
    reduce_head_kernel<<<N_ROI, 32>>>(headpart, bloc, bcls, out);
}